// round 15
// baseline (speedup 1.0000x reference)
#include <cuda_runtime.h>
#include <cuda_fp16.h>
#include <cstdint>

#define B_SZ   2
#define T_SZ   2048
#define C_SZ   1024
#define M_ROWS 4096
#define N_QKV  3072
#define GEMM_K 1024

// ---------------------------------------------------------------------------
// Scratch (__device__ globals; no allocation allowed). All fp16 hi-only.
// ---------------------------------------------------------------------------
__device__ __half g_x_hi[M_ROWS * C_SZ];
__device__ __half g_wq_hi[N_QKV * GEMM_K];     // transposed [n][k]
__device__ __half g_wp_hi[C_SZ * GEMM_K];      // transposed [n][k]
// qkv for attention: all hi-only; q pre-scaled by 1/8.  [bh][t][d]
__device__ __half g_k16h[32 * T_SZ * 64];
__device__ __half g_q16h[32 * T_SZ * 64];
__device__ __half g_v16h[32 * T_SZ * 64];
// attention out, fp16 (proj A side), [b][t][C]
__device__ __half g_ao_hi[M_ROWS * C_SZ];

// ---------------------------------------------------------------------------
// PTX helpers (plain sm_103 target)
// ---------------------------------------------------------------------------
#define CP_ASYNC16(dst, src) \
    asm volatile("cp.async.cg.shared.global [%0], [%1], 16;" :: "r"(dst), "l"(src))
#define CP_COMMIT() asm volatile("cp.async.commit_group;" ::: "memory")
#define CP_WAIT1()  asm volatile("cp.async.wait_group 1;" ::: "memory")
#define CP_WAIT0()  asm volatile("cp.async.wait_group 0;" ::: "memory")

__device__ __forceinline__ void ldm_x4(uint32_t* r, uint32_t a) {
    asm volatile("ldmatrix.sync.aligned.m8n8.x4.shared.b16 {%0,%1,%2,%3}, [%4];"
                 : "=r"(r[0]), "=r"(r[1]), "=r"(r[2]), "=r"(r[3]) : "r"(a));
}
__device__ __forceinline__ void ldm_x4t(uint32_t* r, uint32_t a) {
    asm volatile("ldmatrix.sync.aligned.m8n8.x4.trans.shared.b16 {%0,%1,%2,%3}, [%4];"
                 : "=r"(r[0]), "=r"(r[1]), "=r"(r[2]), "=r"(r[3]) : "r"(a));
}
__device__ __forceinline__ void mma_f16(float* d, const uint32_t* a,
                                        const uint32_t* b) {
    asm volatile(
        "mma.sync.aligned.m16n8k16.row.col.f32.f16.f16.f32 "
        "{%0,%1,%2,%3}, {%4,%5,%6,%7}, {%8,%9}, {%0,%1,%2,%3};"
        : "+f"(d[0]), "+f"(d[1]), "+f"(d[2]), "+f"(d[3])
        : "r"(a[0]), "r"(a[1]), "r"(a[2]), "r"(a[3]), "r"(b[0]), "r"(b[1]));
}
__device__ __forceinline__ uint32_t packh(float f0, float f1) {
    __half2 t = __floats2half2_rn(f0, f1);
    return *reinterpret_cast<uint32_t*>(&t);
}

// ---------------------------------------------------------------------------
// Fused prep: x -> fp16; wq/wp -> transposed fp16.
// blocks [0,16384): x   [16384,19456): wq   [19456,20480): wp
// ---------------------------------------------------------------------------
__global__ __launch_bounds__(256)
void prep_kernel(const float* __restrict__ x,
                 const float* __restrict__ wq,
                 const float* __restrict__ wp) {
    __shared__ float tile[32][33];
    const int blk = blockIdx.x;
    const int tid = threadIdx.x;

    if (blk < 16384) {
        int i = blk * 256 + tid;
        g_x_hi[i] = __float2half_rn(x[i]);
        return;
    }

    const float* w;
    __half* oh;
    int N, bb;
    if (blk < 16384 + 3072) {
        bb = blk - 16384; w = wq; oh = g_wq_hi; N = N_QKV;
    } else {
        bb = blk - 19456; w = wp; oh = g_wp_hi; N = C_SZ;
    }
    const int nb = (bb % (N / 32)) * 32;
    const int kb = (bb / (N / 32)) * 32;
    const int tx = tid & 31, ty = tid >> 5;
#pragma unroll
    for (int i2 = 0; i2 < 32; i2 += 8)
        tile[ty + i2][tx] = w[(size_t)(kb + ty + i2) * N + nb + tx];
    __syncthreads();
#pragma unroll
    for (int i2 = 0; i2 < 32; i2 += 8)
        oh[(size_t)(nb + ty + i2) * GEMM_K + kb + tx] =
            __float2half_rn(tile[tx][ty + i2]);
}

// ---------------------------------------------------------------------------
// HMMA 1-pass fp16 GEMM: C = Ah @ Bh^T.  128x128 CTA tile, BK=64, 3-stage
// cp.async.  128 threads = 4 warps (2x2), warp tile 64x64: 8 LDSM.x4 feed 32
// HMMA per k-step (4:1 ratio, long MMA bursts).  2 CTAs/SM, independent
// barriers.
// mode 0: bias + fp16 scatter (k hi, q hi*0.125, v hi)
// mode 1: bias + fp32 store
// ---------------------------------------------------------------------------
#define G_ROWB   144                    // 128B data + 16B pad
#define G_TILE   (128 * G_ROWB)         // 18432
#define G_STAGE  (2 * G_TILE)           // 36864 (Ah, Bh)
#define GEMM_SMEM (3 * G_STAGE)         // 110592 -> 2 CTAs/SM

__global__ __launch_bounds__(128, 2)
void gemm_hmma(const float* __restrict__ bias, float* __restrict__ out,
               int mode) {
    extern __shared__ char smem[];
    const uint32_t sbase = (uint32_t)__cvta_generic_to_shared(smem);
    const int tid = threadIdx.x;
    const int lane = tid & 31, warp = tid >> 5;
    const int wr = warp & 1, wc = warp >> 1;      // 2x2 warp grid, warp 64x64
    const int rowBase = blockIdx.y * 128;
    const int colBase = blockIdx.x * 128;

    const __half *aSrc, *bSrc;
    if (mode == 0) { aSrc = g_x_hi;  bSrc = g_wq_hi; }
    else           { aSrc = g_ao_hi; bSrc = g_wp_hi; }

    float acc[4][8][4];
#pragma unroll
    for (int mt = 0; mt < 4; mt++)
#pragma unroll
        for (int nt = 0; nt < 8; nt++)
#pragma unroll
            for (int q = 0; q < 4; q++) acc[mt][nt][q] = 0.f;

    // per chunk: A 128x128B + B 128x128B = 32KB; 128 thr x 16 x 16B
    auto prefetch = [&](int chunk) {
        const int st = chunk % 3;
        const int k0 = chunk * 64;
        const int rb[2] = {rowBase, colBase};
        const __half* sv[2] = {aSrc, bSrc};
#pragma unroll
        for (int v = 0; v < 2; v++) {
#pragma unroll
            for (int it = 0; it < 8; it++) {
                int p = tid + it * 128;            // 0..1023
                int r = p >> 3, cp = p & 7;
                const __half* g =
                    sv[v] + (size_t)(rb[v] + r) * GEMM_K + k0 + cp * 8;
                uint32_t d = sbase + (uint32_t)(st * G_STAGE + v * G_TILE
                                                + r * G_ROWB + cp * 16);
                CP_ASYNC16(d, g);
            }
        }
        CP_COMMIT();
    };

    prefetch(0);
    prefetch(1);

    const int NC = GEMM_K / 64;          // 16
    for (int c = 0; c < NC; c++) {
        if (c + 1 < NC) { CP_WAIT1(); } else { CP_WAIT0(); }
        __syncthreads();
        if (c + 2 < NC) prefetch(c + 2);  // writes stage (c+2)%3 = (c-1)%3: safe

        const uint32_t bufBase = sbase + (uint32_t)((c % 3) * G_STAGE);
#pragma unroll
        for (int s = 0; s < 4; s++) {
            uint32_t ah[4][4], bh[4][4];
            const int akb = s * 32 + ((lane >> 4) & 1) * 16;
            const int arow = wr * 64 + (lane & 7) + ((lane >> 3) & 1) * 8;
#pragma unroll
            for (int mf = 0; mf < 4; mf++)
                ldm_x4(ah[mf], bufBase + (uint32_t)((arow + mf * 16) * G_ROWB + akb));

            const int bkb = s * 32 + ((lane >> 3) & 1) * 16;
            const int brow = wc * 64 + ((lane >> 4) & 1) * 8 + (lane & 7);
#pragma unroll
            for (int p2 = 0; p2 < 4; p2++)
                ldm_x4(bh[p2], bufBase + (uint32_t)(G_TILE + (brow + p2 * 16) * G_ROWB + bkb));

#pragma unroll
            for (int mt = 0; mt < 4; mt++)
#pragma unroll
                for (int nt = 0; nt < 8; nt++)
                    mma_f16(acc[mt][nt], ah[mt], &bh[nt >> 1][(nt & 1) * 2]);
        }
    }

    const int r0 = lane >> 2;
    const int c0 = (lane & 3) * 2;
#pragma unroll
    for (int mt = 0; mt < 4; mt++) {
#pragma unroll
        for (int nt = 0; nt < 8; nt++) {
            const int n0 = colBase + wc * 64 + nt * 8 + c0;
            const float b0 = bias[n0], b1 = bias[n0 + 1];
#pragma unroll
            for (int half = 0; half < 2; half++) {
                const int m = rowBase + wr * 64 + mt * 16 + r0 + half * 8;
                float f0 = acc[mt][nt][half * 2 + 0] + b0;
                float f1 = acc[mt][nt][half * 2 + 1] + b1;
                if (mode == 0) {
                    const int bb = m >> 11, t = m & 2047;
                    const int sec = n0 >> 10, cc = n0 & 1023;
                    const int h = cc >> 6, d0 = cc & 63;
                    size_t off = (((size_t)(bb * 16 + h)) * T_SZ + t) * 64 + d0;
                    if (sec == 1) {
                        *(uint32_t*)(g_q16h + off) = packh(f0 * 0.125f, f1 * 0.125f);
                    } else {
                        __half* dh = (sec == 0) ? g_k16h : g_v16h;
                        *(uint32_t*)(dh + off) = packh(f0, f1);
                    }
                } else {
                    float2 v; v.x = f0; v.y = f1;
                    *(float2*)(out + (size_t)m * C_SZ + n0) = v;
                }
            }
        }
    }
}

// ---------------------------------------------------------------------------
// Flash attention v6: fully 1-pass fp16, resident-K fragments hoisted out of
// the j-loop (jt-invariant; saves 8 of 40 LDSM.x4 per j-tile).
// 256-row i-tiles, 8 warps x 32 rows. wei = K@Q^T: query-role = k (resident),
// key-role = q (pre-scaled). S = Kh·Qh;  O = Ph·Vh.
// ---------------------------------------------------------------------------
#define AST   144
#define SQH_O 0
#define SKV_O (256 * AST)              // 36864
#define KVVAR (64 * AST)               // 9216
#define KVBUF (2 * KVVAR)              // 18432 (qh, vh)
#define ATT_SMEM (SKV_O + 2 * KVBUF)   // 73728

__global__ __launch_bounds__(256, 1)
void attn_hmma() {
    extern __shared__ char smem[];
    const uint32_t sbase = (uint32_t)__cvta_generic_to_shared(smem);
    const int tid = threadIdx.x;
    const int lane = tid & 31, w = tid >> 5;
    const int bh = blockIdx.x;
    const int it = (int)(gridDim.y - 1 - blockIdx.y);   // heavy blocks first

    const size_t hbo = (size_t)bh * T_SZ * 64;
    const __half* kvsrc[2] = {g_q16h + hbo, g_v16h + hbo};

    auto prefetchKV = [&](int jt) {
        const int buf = jt & 1;
#pragma unroll
        for (int i = 0; i < 4; i++) {
            int p = tid + i * 256;               // 0..1023
            int v = p >> 9, rem = p & 511;
            int r = rem >> 3, cp = rem & 7;
            const __half* src = kvsrc[v] + (size_t)(jt * 64 + r) * 64 + cp * 8;
            uint32_t dst = sbase + (uint32_t)(SKV_O + buf * KVBUF + v * KVVAR
                                              + r * AST + cp * 16);
            CP_ASYNC16(dst, src);
        }
        CP_COMMIT();
    };

    prefetchKV(0);

    // resident query-role tile (k hi)
    {
        const __half* kh = g_k16h + hbo;
        for (int p = tid; p < 256 * 32; p += 256) {
            int r = p >> 5, c2 = p & 31;
            size_t go = (size_t)(it * 256 + r) * 64 + c2 * 2;
            *(uint32_t*)(smem + SQH_O + r * AST + c2 * 4) = *(const uint32_t*)(kh + go);
        }
    }
    __syncthreads();

    // Hoisted K fragments (jt-invariant)
    uint32_t kf[4][2][4];
    {
        const int arow = w * 32 + (lane & 7) + ((lane >> 3) & 1) * 8;
#pragma unroll
        for (int kk = 0; kk < 4; kk++) {
            const int ab = kk * 32 + ((lane >> 4) & 1) * 16;
            ldm_x4(kf[kk][0], sbase + (uint32_t)(SQH_O + arow * AST + ab));
            ldm_x4(kf[kk][1], sbase + (uint32_t)(SQH_O + (arow + 16) * AST + ab));
        }
    }

    float m[2][2], l[2][2];
#pragma unroll
    for (int mt = 0; mt < 2; mt++) { m[mt][0] = m[mt][1] = -1e30f; l[mt][0] = l[mt][1] = 0.f; }
    float O[2][8][4];
#pragma unroll
    for (int mt = 0; mt < 2; mt++)
#pragma unroll
        for (int dt = 0; dt < 8; dt++)
#pragma unroll
            for (int q = 0; q < 4; q++) O[mt][dt][q] = 0.f;

    const int iw = it * 256 + w * 32;
    const int jlast = 4 * it + 3;

    for (int jt = 0; jt <= jlast; jt++) {
        CP_WAIT0();
        __syncthreads();
        if (jt < jlast) prefetchKV(jt + 1);

        if (jt * 64 <= iw + 31) {
            const uint32_t kb = sbase + (uint32_t)(SKV_O + (jt & 1) * KVBUF);
            float s[2][8][4];
#pragma unroll
            for (int mt = 0; mt < 2; mt++)
#pragma unroll
                for (int nt = 0; nt < 8; nt++)
#pragma unroll
                    for (int q = 0; q < 4; q++) s[mt][nt][q] = 0.f;

            // ---- scores: S = Kh @ Qh^T (1 pass, K frags from registers) ----
#pragma unroll
            for (int kk = 0; kk < 4; kk++) {
                const int bb = kk * 32 + ((lane >> 3) & 1) * 16;
                const int br = ((lane >> 4) & 1) * 8 + (lane & 7);
#pragma unroll
                for (int np = 0; np < 4; np++) {
                    uint32_t qf[4];
                    ldm_x4(qf, kb + (uint32_t)((np * 16 + br) * AST + bb));
#pragma unroll
                    for (int mt = 0; mt < 2; mt++) {
                        mma_f16(s[mt][2 * np],     kf[kk][mt], qf + 0);
                        mma_f16(s[mt][2 * np + 1], kf[kk][mt], qf + 2);
                    }
                }
            }

            // ---- causal mask ----
            const int i0 = iw + (lane >> 2);
            if (jt * 64 + 63 > iw) {
#pragma unroll
                for (int mt = 0; mt < 2; mt++)
#pragma unroll
                    for (int nt = 0; nt < 8; nt++)
#pragma unroll
                        for (int q = 0; q < 4; q++) {
                            int j = jt * 64 + nt * 8 + (lane & 3) * 2 + (q & 1);
                            int i = i0 + mt * 16 + ((q >> 1) ? 8 : 0);
                            if (j > i) s[mt][nt][q] = -1e30f;
                        }
            }

            // ---- online softmax ----
#pragma unroll
            for (int mt = 0; mt < 2; mt++) {
                float mx0 = -1e30f, mx1 = -1e30f;
#pragma unroll
                for (int nt = 0; nt < 8; nt++) {
                    mx0 = fmaxf(mx0, fmaxf(s[mt][nt][0], s[mt][nt][1]));
                    mx1 = fmaxf(mx1, fmaxf(s[mt][nt][2], s[mt][nt][3]));
                }
                mx0 = fmaxf(mx0, __shfl_xor_sync(0xffffffffu, mx0, 1));
                mx0 = fmaxf(mx0, __shfl_xor_sync(0xffffffffu, mx0, 2));
                mx1 = fmaxf(mx1, __shfl_xor_sync(0xffffffffu, mx1, 1));
                mx1 = fmaxf(mx1, __shfl_xor_sync(0xffffffffu, mx1, 2));
                float mn0 = fmaxf(m[mt][0], mx0), mn1 = fmaxf(m[mt][1], mx1);
                float a0 = __expf(m[mt][0] - mn0), a1 = __expf(m[mt][1] - mn1);
                float sum0 = 0.f, sum1 = 0.f;
#pragma unroll
                for (int nt = 0; nt < 8; nt++) {
                    s[mt][nt][0] = __expf(s[mt][nt][0] - mn0);
                    s[mt][nt][1] = __expf(s[mt][nt][1] - mn0);
                    s[mt][nt][2] = __expf(s[mt][nt][2] - mn1);
                    s[mt][nt][3] = __expf(s[mt][nt][3] - mn1);
                    sum0 += s[mt][nt][0] + s[mt][nt][1];
                    sum1 += s[mt][nt][2] + s[mt][nt][3];
                }
                sum0 += __shfl_xor_sync(0xffffffffu, sum0, 1);
                sum0 += __shfl_xor_sync(0xffffffffu, sum0, 2);
                sum1 += __shfl_xor_sync(0xffffffffu, sum1, 1);
                sum1 += __shfl_xor_sync(0xffffffffu, sum1, 2);
                l[mt][0] = l[mt][0] * a0 + sum0;
                l[mt][1] = l[mt][1] * a1 + sum1;
                m[mt][0] = mn0;  m[mt][1] = mn1;
#pragma unroll
                for (int dt = 0; dt < 8; dt++) {
                    O[mt][dt][0] *= a0; O[mt][dt][1] *= a0;
                    O[mt][dt][2] *= a1; O[mt][dt][3] *= a1;
                }
            }

            // ---- PV: O += Ph @ Vh (1 pass) ----
#pragma unroll
            for (int kk = 0; kk < 4; kk++) {
                uint32_t pah[2][4];
#pragma unroll
                for (int mt = 0; mt < 2; mt++)
#pragma unroll
                    for (int t = 0; t < 4; t++) {
                        float f0 = s[mt][2 * kk + (t >> 1)][(t & 1) * 2 + 0];
                        float f1 = s[mt][2 * kk + (t >> 1)][(t & 1) * 2 + 1];
                        pah[mt][t] = packh(f0, f1);
                    }
                const int vrow = kk * 16 + (lane & 7) + ((lane >> 3) & 1) * 8;
                const int voff = ((lane >> 4) & 1) * 16;
#pragma unroll
                for (int dp = 0; dp < 4; dp++) {
                    uint32_t vh4[4];
                    ldm_x4t(vh4, kb + (uint32_t)(KVVAR + vrow * AST + dp * 32 + voff));
#pragma unroll
                    for (int mt = 0; mt < 2; mt++) {
                        mma_f16(O[mt][2 * dp],     pah[mt], vh4 + 0);
                        mma_f16(O[mt][2 * dp + 1], pah[mt], vh4 + 2);
                    }
                }
            }
        }
    }

    // epilogue: normalize, fp16 write [b][t][C]
    const int b = bh >> 4, h = bh & 15;
#pragma unroll
    for (int mt = 0; mt < 2; mt++) {
        const float inv0 = 1.f / l[mt][0], inv1 = 1.f / l[mt][1];
        const int i0 = iw + mt * 16 + (lane >> 2);
#pragma unroll
        for (int dt = 0; dt < 8; dt++) {
            const int col = h * 64 + dt * 8 + (lane & 3) * 2;
            {
                float f0 = O[mt][dt][0] * inv0, f1 = O[mt][dt][1] * inv0;
                size_t off = ((size_t)(b * T_SZ + i0)) * C_SZ + col;
                *(uint32_t*)(g_ao_hi + off) = packh(f0, f1);
            }
            {
                float f0 = O[mt][dt][2] * inv1, f1 = O[mt][dt][3] * inv1;
                size_t off = ((size_t)(b * T_SZ + i0 + 8)) * C_SZ + col;
                *(uint32_t*)(g_ao_hi + off) = packh(f0, f1);
            }
        }
    }
}

// ---------------------------------------------------------------------------
extern "C" void kernel_launch(void* const* d_in, const int* in_sizes, int n_in,
                              void* d_out, int out_size) {
    const float* x        = (const float*)d_in[0];
    const float* c_attn_w = (const float*)d_in[1];
    const float* c_attn_b = (const float*)d_in[2];
    const float* c_proj_w = (const float*)d_in[3];
    const float* c_proj_b = (const float*)d_in[4];
    float* out = (float*)d_out;

    prep_kernel<<<16384 + 3072 + 1024, 256>>>(x, c_attn_w, c_proj_w);

    cudaFuncSetAttribute(gemm_hmma,
                         cudaFuncAttributeMaxDynamicSharedMemorySize, GEMM_SMEM);
    cudaFuncSetAttribute(attn_hmma,
                         cudaFuncAttributeMaxDynamicSharedMemorySize, ATT_SMEM);

    // QKV: grid (24, 32), 128 threads
    gemm_hmma<<<dim3(N_QKV / 128, M_ROWS / 128), 128, GEMM_SMEM>>>(
        c_attn_b, nullptr, 0);

    attn_hmma<<<dim3(32, T_SZ / 256), 256, ATT_SMEM>>>();

    // Proj: grid (8, 32)
    gemm_hmma<<<dim3(C_SZ / 128, M_ROWS / 128), 128, GEMM_SMEM>>>(
        c_proj_b, out, 1);
}

// round 16
// speedup vs baseline: 1.0711x; 1.0711x over previous
#include <cuda_runtime.h>
#include <cuda_fp16.h>
#include <cstdint>

#define B_SZ   2
#define T_SZ   2048
#define C_SZ   1024
#define M_ROWS 4096
#define N_QKV  3072
#define GEMM_K 1024

// ---------------------------------------------------------------------------
// Scratch (__device__ globals; no allocation allowed). All fp16 hi-only.
// ---------------------------------------------------------------------------
__device__ __half g_x_hi[M_ROWS * C_SZ];
__device__ __half g_wq_hi[N_QKV * GEMM_K];     // transposed [n][k]
__device__ __half g_wp_hi[C_SZ * GEMM_K];      // transposed [n][k]
// qkv for attention: all hi-only; q pre-scaled by 1/8.  [bh][t][d]
__device__ __half g_k16h[32 * T_SZ * 64];
__device__ __half g_q16h[32 * T_SZ * 64];
__device__ __half g_v16h[32 * T_SZ * 64];
// attention out, fp16 (proj A side), [b][t][C]
__device__ __half g_ao_hi[M_ROWS * C_SZ];

// ---------------------------------------------------------------------------
// PTX helpers (plain sm_103 target)
// ---------------------------------------------------------------------------
#define CP_ASYNC16(dst, src) \
    asm volatile("cp.async.cg.shared.global [%0], [%1], 16;" :: "r"(dst), "l"(src))
#define CP_COMMIT() asm volatile("cp.async.commit_group;" ::: "memory")
#define CP_WAIT1()  asm volatile("cp.async.wait_group 1;" ::: "memory")
#define CP_WAIT0()  asm volatile("cp.async.wait_group 0;" ::: "memory")

__device__ __forceinline__ void ldm_x4(uint32_t* r, uint32_t a) {
    asm volatile("ldmatrix.sync.aligned.m8n8.x4.shared.b16 {%0,%1,%2,%3}, [%4];"
                 : "=r"(r[0]), "=r"(r[1]), "=r"(r[2]), "=r"(r[3]) : "r"(a));
}
__device__ __forceinline__ void ldm_x4t(uint32_t* r, uint32_t a) {
    asm volatile("ldmatrix.sync.aligned.m8n8.x4.trans.shared.b16 {%0,%1,%2,%3}, [%4];"
                 : "=r"(r[0]), "=r"(r[1]), "=r"(r[2]), "=r"(r[3]) : "r"(a));
}
__device__ __forceinline__ void mma_f16(float* d, const uint32_t* a,
                                        const uint32_t* b) {
    asm volatile(
        "mma.sync.aligned.m16n8k16.row.col.f32.f16.f16.f32 "
        "{%0,%1,%2,%3}, {%4,%5,%6,%7}, {%8,%9}, {%0,%1,%2,%3};"
        : "+f"(d[0]), "+f"(d[1]), "+f"(d[2]), "+f"(d[3])
        : "r"(a[0]), "r"(a[1]), "r"(a[2]), "r"(a[3]), "r"(b[0]), "r"(b[1]));
}
__device__ __forceinline__ uint32_t packh(float f0, float f1) {
    __half2 t = __floats2half2_rn(f0, f1);
    return *reinterpret_cast<uint32_t*>(&t);
}

// ---------------------------------------------------------------------------
// Fused prep: x -> fp16 (vectorized); wq/wp -> transposed fp16.
// blocks [0,4096): x (float4 per thread)  [4096,7168): wq  [7168,8192): wp
// ---------------------------------------------------------------------------
__global__ __launch_bounds__(256)
void prep_kernel(const float* __restrict__ x,
                 const float* __restrict__ wq,
                 const float* __restrict__ wp) {
    __shared__ float tile[32][33];
    const int blk = blockIdx.x;
    const int tid = threadIdx.x;

    if (blk < 4096) {
        int i = (blk * 256 + tid) * 4;
        float4 v = *(const float4*)(x + i);
        *(__half2*)(g_x_hi + i)     = __floats2half2_rn(v.x, v.y);
        *(__half2*)(g_x_hi + i + 2) = __floats2half2_rn(v.z, v.w);
        return;
    }

    const float* w;
    __half* oh;
    int N, bb;
    if (blk < 4096 + 3072) {
        bb = blk - 4096; w = wq; oh = g_wq_hi; N = N_QKV;
    } else {
        bb = blk - 7168; w = wp; oh = g_wp_hi; N = C_SZ;
    }
    const int nb = (bb % (N / 32)) * 32;
    const int kb = (bb / (N / 32)) * 32;
    const int tx = tid & 31, ty = tid >> 5;
#pragma unroll
    for (int i2 = 0; i2 < 32; i2 += 8)
        tile[ty + i2][tx] = w[(size_t)(kb + ty + i2) * N + nb + tx];
    __syncthreads();
#pragma unroll
    for (int i2 = 0; i2 < 32; i2 += 8)
        oh[(size_t)(nb + ty + i2) * GEMM_K + kb + tx] =
            __float2half_rn(tile[tx][ty + i2]);
}

// ---------------------------------------------------------------------------
// HMMA 1-pass fp16 GEMM: C = Ah @ Bh^T.  128x128 CTA tile, BK=64, 3-stage
// cp.async, 256 threads (8 warps 4x2, warp 32x64), 2 CTAs/SM, with 2-deep
// register fragment pipeline (LDSM for k-step s+1 in flight during MMAs of s).
// mode 0: bias + fp16 scatter (k hi, q hi*0.125, v hi)
// mode 1: bias + fp32 store
// ---------------------------------------------------------------------------
#define G_ROWB   144                    // 128B data + 16B pad
#define G_TILE   (128 * G_ROWB)         // 18432
#define G_STAGE  (2 * G_TILE)           // 36864 (Ah, Bh)
#define GEMM_SMEM (3 * G_STAGE)         // 110592 -> 2 CTAs/SM

struct GFrag { uint32_t a[2][4]; uint32_t b[4][4]; };   // 24 regs

__device__ __forceinline__ void g_load(GFrag& F, uint32_t bufBase, int s,
                                       int wr, int wc, int lane) {
    const int akb = s * 32 + ((lane >> 4) & 1) * 16;
    const int arow = wr * 32 + (lane & 7) + ((lane >> 3) & 1) * 8;
    ldm_x4(F.a[0], bufBase + (uint32_t)(arow * G_ROWB + akb));
    ldm_x4(F.a[1], bufBase + (uint32_t)((arow + 16) * G_ROWB + akb));
    const int bkb = s * 32 + ((lane >> 3) & 1) * 16;
    const int brow = wc * 64 + ((lane >> 4) & 1) * 8 + (lane & 7);
#pragma unroll
    for (int p2 = 0; p2 < 4; p2++)
        ldm_x4(F.b[p2], bufBase + (uint32_t)(G_TILE + (brow + p2 * 16) * G_ROWB + bkb));
}

__device__ __forceinline__ void g_mma(float acc[2][8][4], const GFrag& F) {
#pragma unroll
    for (int mt = 0; mt < 2; mt++)
#pragma unroll
        for (int nt = 0; nt < 8; nt++)
            mma_f16(acc[mt][nt], F.a[mt], &F.b[nt >> 1][(nt & 1) * 2]);
}

__global__ __launch_bounds__(256, 2)
void gemm_hmma(const float* __restrict__ bias, float* __restrict__ out,
               int mode) {
    extern __shared__ char smem[];
    const uint32_t sbase = (uint32_t)__cvta_generic_to_shared(smem);
    const int tid = threadIdx.x;
    const int lane = tid & 31, warp = tid >> 5;
    const int wr = warp & 3, wc = warp >> 2;      // 4x2 warp grid, warp 32x64
    const int rowBase = blockIdx.y * 128;
    const int colBase = blockIdx.x * 128;

    const __half *aSrc, *bSrc;
    if (mode == 0) { aSrc = g_x_hi;  bSrc = g_wq_hi; }
    else           { aSrc = g_ao_hi; bSrc = g_wp_hi; }

    float acc[2][8][4];
#pragma unroll
    for (int mt = 0; mt < 2; mt++)
#pragma unroll
        for (int nt = 0; nt < 8; nt++)
#pragma unroll
            for (int q = 0; q < 4; q++) acc[mt][nt][q] = 0.f;

    auto prefetch = [&](int chunk) {
        const int st = chunk % 3;
        const int k0 = chunk * 64;
        const int rb[2] = {rowBase, colBase};
        const __half* sv[2] = {aSrc, bSrc};
#pragma unroll
        for (int v = 0; v < 2; v++) {
#pragma unroll
            for (int it = 0; it < 4; it++) {
                int p = tid + it * 256;            // 0..1023
                int r = p >> 3, cp = p & 7;
                const __half* g =
                    sv[v] + (size_t)(rb[v] + r) * GEMM_K + k0 + cp * 8;
                uint32_t d = sbase + (uint32_t)(st * G_STAGE + v * G_TILE
                                                + r * G_ROWB + cp * 16);
                CP_ASYNC16(d, g);
            }
        }
        CP_COMMIT();
    };

    prefetch(0);
    prefetch(1);

    GFrag F0, F1;
    const int NC = GEMM_K / 64;          // 16
    for (int c = 0; c < NC; c++) {
        if (c + 1 < NC) { CP_WAIT1(); } else { CP_WAIT0(); }
        __syncthreads();
        if (c + 2 < NC) prefetch(c + 2);  // writes stage (c+2)%3 = (c-1)%3: safe

        const uint32_t bufBase = sbase + (uint32_t)((c % 3) * G_STAGE);
        g_load(F0, bufBase, 0, wr, wc, lane);
        g_load(F1, bufBase, 1, wr, wc, lane);  // in flight during s=0 MMAs
        g_mma(acc, F0);
        g_load(F0, bufBase, 2, wr, wc, lane);
        g_mma(acc, F1);
        g_load(F1, bufBase, 3, wr, wc, lane);
        g_mma(acc, F0);
        g_mma(acc, F1);
    }

    const int r0 = lane >> 2;
    const int c0 = (lane & 3) * 2;
#pragma unroll
    for (int mt = 0; mt < 2; mt++) {
#pragma unroll
        for (int nt = 0; nt < 8; nt++) {
            const int n0 = colBase + wc * 64 + nt * 8 + c0;
            const float b0 = bias[n0], b1 = bias[n0 + 1];
#pragma unroll
            for (int half = 0; half < 2; half++) {
                const int m = rowBase + wr * 32 + mt * 16 + r0 + half * 8;
                float f0 = acc[mt][nt][half * 2 + 0] + b0;
                float f1 = acc[mt][nt][half * 2 + 1] + b1;
                if (mode == 0) {
                    const int bb = m >> 11, t = m & 2047;
                    const int sec = n0 >> 10, cc = n0 & 1023;
                    const int h = cc >> 6, d0 = cc & 63;
                    size_t off = (((size_t)(bb * 16 + h)) * T_SZ + t) * 64 + d0;
                    if (sec == 1) {
                        *(uint32_t*)(g_q16h + off) = packh(f0 * 0.125f, f1 * 0.125f);
                    } else {
                        __half* dh = (sec == 0) ? g_k16h : g_v16h;
                        *(uint32_t*)(dh + off) = packh(f0, f1);
                    }
                } else {
                    float2 v; v.x = f0; v.y = f1;
                    *(float2*)(out + (size_t)m * C_SZ + n0) = v;
                }
            }
        }
    }
}

// ---------------------------------------------------------------------------
// Flash attention (round-15 version: 1-pass fp16, hoisted K fragments).
// 256-row i-tiles, 8 warps x 32 rows. wei = K@Q^T: query-role = k (resident),
// key-role = q (pre-scaled). S = Kh·Qh;  O = Ph·Vh.
// ---------------------------------------------------------------------------
#define AST   144
#define SQH_O 0
#define SKV_O (256 * AST)              // 36864
#define KVVAR (64 * AST)               // 9216
#define KVBUF (2 * KVVAR)              // 18432 (qh, vh)
#define ATT_SMEM (SKV_O + 2 * KVBUF)   // 73728

__global__ __launch_bounds__(256, 1)
void attn_hmma() {
    extern __shared__ char smem[];
    const uint32_t sbase = (uint32_t)__cvta_generic_to_shared(smem);
    const int tid = threadIdx.x;
    const int lane = tid & 31, w = tid >> 5;
    const int bh = blockIdx.x;
    const int it = (int)(gridDim.y - 1 - blockIdx.y);   // heavy blocks first

    const size_t hbo = (size_t)bh * T_SZ * 64;
    const __half* kvsrc[2] = {g_q16h + hbo, g_v16h + hbo};

    auto prefetchKV = [&](int jt) {
        const int buf = jt & 1;
#pragma unroll
        for (int i = 0; i < 4; i++) {
            int p = tid + i * 256;               // 0..1023
            int v = p >> 9, rem = p & 511;
            int r = rem >> 3, cp = rem & 7;
            const __half* src = kvsrc[v] + (size_t)(jt * 64 + r) * 64 + cp * 8;
            uint32_t dst = sbase + (uint32_t)(SKV_O + buf * KVBUF + v * KVVAR
                                              + r * AST + cp * 16);
            CP_ASYNC16(dst, src);
        }
        CP_COMMIT();
    };

    prefetchKV(0);

    {
        const __half* kh = g_k16h + hbo;
        for (int p = tid; p < 256 * 32; p += 256) {
            int r = p >> 5, c2 = p & 31;
            size_t go = (size_t)(it * 256 + r) * 64 + c2 * 2;
            *(uint32_t*)(smem + SQH_O + r * AST + c2 * 4) = *(const uint32_t*)(kh + go);
        }
    }
    __syncthreads();

    uint32_t kf[4][2][4];
    {
        const int arow = w * 32 + (lane & 7) + ((lane >> 3) & 1) * 8;
#pragma unroll
        for (int kk = 0; kk < 4; kk++) {
            const int ab = kk * 32 + ((lane >> 4) & 1) * 16;
            ldm_x4(kf[kk][0], sbase + (uint32_t)(SQH_O + arow * AST + ab));
            ldm_x4(kf[kk][1], sbase + (uint32_t)(SQH_O + (arow + 16) * AST + ab));
        }
    }

    float m[2][2], l[2][2];
#pragma unroll
    for (int mt = 0; mt < 2; mt++) { m[mt][0] = m[mt][1] = -1e30f; l[mt][0] = l[mt][1] = 0.f; }
    float O[2][8][4];
#pragma unroll
    for (int mt = 0; mt < 2; mt++)
#pragma unroll
        for (int dt = 0; dt < 8; dt++)
#pragma unroll
            for (int q = 0; q < 4; q++) O[mt][dt][q] = 0.f;

    const int iw = it * 256 + w * 32;
    const int jlast = 4 * it + 3;

    for (int jt = 0; jt <= jlast; jt++) {
        CP_WAIT0();
        __syncthreads();
        if (jt < jlast) prefetchKV(jt + 1);

        if (jt * 64 <= iw + 31) {
            const uint32_t kb = sbase + (uint32_t)(SKV_O + (jt & 1) * KVBUF);
            float s[2][8][4];
#pragma unroll
            for (int mt = 0; mt < 2; mt++)
#pragma unroll
                for (int nt = 0; nt < 8; nt++)
#pragma unroll
                    for (int q = 0; q < 4; q++) s[mt][nt][q] = 0.f;

#pragma unroll
            for (int kk = 0; kk < 4; kk++) {
                const int bb = kk * 32 + ((lane >> 3) & 1) * 16;
                const int br = ((lane >> 4) & 1) * 8 + (lane & 7);
#pragma unroll
                for (int np = 0; np < 4; np++) {
                    uint32_t qf[4];
                    ldm_x4(qf, kb + (uint32_t)((np * 16 + br) * AST + bb));
#pragma unroll
                    for (int mt = 0; mt < 2; mt++) {
                        mma_f16(s[mt][2 * np],     kf[kk][mt], qf + 0);
                        mma_f16(s[mt][2 * np + 1], kf[kk][mt], qf + 2);
                    }
                }
            }

            const int i0 = iw + (lane >> 2);
            if (jt * 64 + 63 > iw) {
#pragma unroll
                for (int mt = 0; mt < 2; mt++)
#pragma unroll
                    for (int nt = 0; nt < 8; nt++)
#pragma unroll
                        for (int q = 0; q < 4; q++) {
                            int j = jt * 64 + nt * 8 + (lane & 3) * 2 + (q & 1);
                            int i = i0 + mt * 16 + ((q >> 1) ? 8 : 0);
                            if (j > i) s[mt][nt][q] = -1e30f;
                        }
            }

#pragma unroll
            for (int mt = 0; mt < 2; mt++) {
                float mx0 = -1e30f, mx1 = -1e30f;
#pragma unroll
                for (int nt = 0; nt < 8; nt++) {
                    mx0 = fmaxf(mx0, fmaxf(s[mt][nt][0], s[mt][nt][1]));
                    mx1 = fmaxf(mx1, fmaxf(s[mt][nt][2], s[mt][nt][3]));
                }
                mx0 = fmaxf(mx0, __shfl_xor_sync(0xffffffffu, mx0, 1));
                mx0 = fmaxf(mx0, __shfl_xor_sync(0xffffffffu, mx0, 2));
                mx1 = fmaxf(mx1, __shfl_xor_sync(0xffffffffu, mx1, 1));
                mx1 = fmaxf(mx1, __shfl_xor_sync(0xffffffffu, mx1, 2));
                float mn0 = fmaxf(m[mt][0], mx0), mn1 = fmaxf(m[mt][1], mx1);
                float a0 = __expf(m[mt][0] - mn0), a1 = __expf(m[mt][1] - mn1);
                float sum0 = 0.f, sum1 = 0.f;
#pragma unroll
                for (int nt = 0; nt < 8; nt++) {
                    s[mt][nt][0] = __expf(s[mt][nt][0] - mn0);
                    s[mt][nt][1] = __expf(s[mt][nt][1] - mn0);
                    s[mt][nt][2] = __expf(s[mt][nt][2] - mn1);
                    s[mt][nt][3] = __expf(s[mt][nt][3] - mn1);
                    sum0 += s[mt][nt][0] + s[mt][nt][1];
                    sum1 += s[mt][nt][2] + s[mt][nt][3];
                }
                sum0 += __shfl_xor_sync(0xffffffffu, sum0, 1);
                sum0 += __shfl_xor_sync(0xffffffffu, sum0, 2);
                sum1 += __shfl_xor_sync(0xffffffffu, sum1, 1);
                sum1 += __shfl_xor_sync(0xffffffffu, sum1, 2);
                l[mt][0] = l[mt][0] * a0 + sum0;
                l[mt][1] = l[mt][1] * a1 + sum1;
                m[mt][0] = mn0;  m[mt][1] = mn1;
#pragma unroll
                for (int dt = 0; dt < 8; dt++) {
                    O[mt][dt][0] *= a0; O[mt][dt][1] *= a0;
                    O[mt][dt][2] *= a1; O[mt][dt][3] *= a1;
                }
            }

#pragma unroll
            for (int kk = 0; kk < 4; kk++) {
                uint32_t pah[2][4];
#pragma unroll
                for (int mt = 0; mt < 2; mt++)
#pragma unroll
                    for (int t = 0; t < 4; t++) {
                        float f0 = s[mt][2 * kk + (t >> 1)][(t & 1) * 2 + 0];
                        float f1 = s[mt][2 * kk + (t >> 1)][(t & 1) * 2 + 1];
                        pah[mt][t] = packh(f0, f1);
                    }
                const int vrow = kk * 16 + (lane & 7) + ((lane >> 3) & 1) * 8;
                const int voff = ((lane >> 4) & 1) * 16;
#pragma unroll
                for (int dp = 0; dp < 4; dp++) {
                    uint32_t vh4[4];
                    ldm_x4t(vh4, kb + (uint32_t)(KVVAR + vrow * AST + dp * 32 + voff));
#pragma unroll
                    for (int mt = 0; mt < 2; mt++) {
                        mma_f16(O[mt][2 * dp],     pah[mt], vh4 + 0);
                        mma_f16(O[mt][2 * dp + 1], pah[mt], vh4 + 2);
                    }
                }
            }
        }
    }

    const int b = bh >> 4, h = bh & 15;
#pragma unroll
    for (int mt = 0; mt < 2; mt++) {
        const float inv0 = 1.f / l[mt][0], inv1 = 1.f / l[mt][1];
        const int i0 = iw + mt * 16 + (lane >> 2);
#pragma unroll
        for (int dt = 0; dt < 8; dt++) {
            const int col = h * 64 + dt * 8 + (lane & 3) * 2;
            {
                float f0 = O[mt][dt][0] * inv0, f1 = O[mt][dt][1] * inv0;
                size_t off = ((size_t)(b * T_SZ + i0)) * C_SZ + col;
                *(uint32_t*)(g_ao_hi + off) = packh(f0, f1);
            }
            {
                float f0 = O[mt][dt][2] * inv1, f1 = O[mt][dt][3] * inv1;
                size_t off = ((size_t)(b * T_SZ + i0 + 8)) * C_SZ + col;
                *(uint32_t*)(g_ao_hi + off) = packh(f0, f1);
            }
        }
    }
}

// ---------------------------------------------------------------------------
extern "C" void kernel_launch(void* const* d_in, const int* in_sizes, int n_in,
                              void* d_out, int out_size) {
    const float* x        = (const float*)d_in[0];
    const float* c_attn_w = (const float*)d_in[1];
    const float* c_attn_b = (const float*)d_in[2];
    const float* c_proj_w = (const float*)d_in[3];
    const float* c_proj_b = (const float*)d_in[4];
    float* out = (float*)d_out;

    prep_kernel<<<4096 + 3072 + 1024, 256>>>(x, c_attn_w, c_proj_w);

    cudaFuncSetAttribute(gemm_hmma,
                         cudaFuncAttributeMaxDynamicSharedMemorySize, GEMM_SMEM);
    cudaFuncSetAttribute(attn_hmma,
                         cudaFuncAttributeMaxDynamicSharedMemorySize, ATT_SMEM);

    // QKV: grid (24, 32)
    gemm_hmma<<<dim3(N_QKV / 128, M_ROWS / 128), 256, GEMM_SMEM>>>(
        c_attn_b, nullptr, 0);

    attn_hmma<<<dim3(32, T_SZ / 256), 256, ATT_SMEM>>>();

    // Proj: grid (8, 32)
    gemm_hmma<<<dim3(C_SZ / 128, M_ROWS / 128), 256, GEMM_SMEM>>>(
        c_proj_b, out, 1);
}

// round 17
// speedup vs baseline: 1.0910x; 1.0186x over previous
#include <cuda_runtime.h>
#include <cuda_fp16.h>
#include <cstdint>

#define B_SZ   2
#define T_SZ   2048
#define C_SZ   1024
#define M_ROWS 4096
#define N_QKV  3072
#define GEMM_K 1024

// q pre-scale: (1/sqrt(64)) * log2(e)  -> scores land in log2 domain
#define QSCALE 0.1803368801111727f

// ---------------------------------------------------------------------------
// Scratch (__device__ globals; no allocation allowed). All fp16 hi-only.
// ---------------------------------------------------------------------------
__device__ __half g_x_hi[M_ROWS * C_SZ];
__device__ __half g_wq_hi[N_QKV * GEMM_K];     // transposed [n][k]
__device__ __half g_wp_hi[C_SZ * GEMM_K];      // transposed [n][k]
// qkv for attention: all hi-only; q pre-scaled by QSCALE.  [bh][t][d]
__device__ __half g_k16h[32 * T_SZ * 64];
__device__ __half g_q16h[32 * T_SZ * 64];
__device__ __half g_v16h[32 * T_SZ * 64];
// attention out, fp16 (proj A side), [b][t][C]
__device__ __half g_ao_hi[M_ROWS * C_SZ];

// ---------------------------------------------------------------------------
// PTX helpers (plain sm_103 target)
// ---------------------------------------------------------------------------
#define CP_ASYNC16(dst, src) \
    asm volatile("cp.async.cg.shared.global [%0], [%1], 16;" :: "r"(dst), "l"(src))
#define CP_COMMIT() asm volatile("cp.async.commit_group;" ::: "memory")
#define CP_WAIT1()  asm volatile("cp.async.wait_group 1;" ::: "memory")
#define CP_WAIT0()  asm volatile("cp.async.wait_group 0;" ::: "memory")

__device__ __forceinline__ void ldm_x4(uint32_t* r, uint32_t a) {
    asm volatile("ldmatrix.sync.aligned.m8n8.x4.shared.b16 {%0,%1,%2,%3}, [%4];"
                 : "=r"(r[0]), "=r"(r[1]), "=r"(r[2]), "=r"(r[3]) : "r"(a));
}
__device__ __forceinline__ void ldm_x4t(uint32_t* r, uint32_t a) {
    asm volatile("ldmatrix.sync.aligned.m8n8.x4.trans.shared.b16 {%0,%1,%2,%3}, [%4];"
                 : "=r"(r[0]), "=r"(r[1]), "=r"(r[2]), "=r"(r[3]) : "r"(a));
}
__device__ __forceinline__ void mma_f16(float* d, const uint32_t* a,
                                        const uint32_t* b) {
    asm volatile(
        "mma.sync.aligned.m16n8k16.row.col.f32.f16.f16.f32 "
        "{%0,%1,%2,%3}, {%4,%5,%6,%7}, {%8,%9}, {%0,%1,%2,%3};"
        : "+f"(d[0]), "+f"(d[1]), "+f"(d[2]), "+f"(d[3])
        : "r"(a[0]), "r"(a[1]), "r"(a[2]), "r"(a[3]), "r"(b[0]), "r"(b[1]));
}
__device__ __forceinline__ uint32_t packh(float f0, float f1) {
    __half2 t = __floats2half2_rn(f0, f1);
    return *reinterpret_cast<uint32_t*>(&t);
}

// ---------------------------------------------------------------------------
// Fused prep: x -> fp16 (vectorized); wq/wp -> transposed fp16.
// blocks [0,4096): x (float4 per thread)  [4096,7168): wq  [7168,8192): wp
// ---------------------------------------------------------------------------
__global__ __launch_bounds__(256)
void prep_kernel(const float* __restrict__ x,
                 const float* __restrict__ wq,
                 const float* __restrict__ wp) {
    __shared__ float tile[32][33];
    const int blk = blockIdx.x;
    const int tid = threadIdx.x;

    if (blk < 4096) {
        int i = (blk * 256 + tid) * 4;
        float4 v = *(const float4*)(x + i);
        *(__half2*)(g_x_hi + i)     = __floats2half2_rn(v.x, v.y);
        *(__half2*)(g_x_hi + i + 2) = __floats2half2_rn(v.z, v.w);
        return;
    }

    const float* w;
    __half* oh;
    int N, bb;
    if (blk < 4096 + 3072) {
        bb = blk - 4096; w = wq; oh = g_wq_hi; N = N_QKV;
    } else {
        bb = blk - 7168; w = wp; oh = g_wp_hi; N = C_SZ;
    }
    const int nb = (bb % (N / 32)) * 32;
    const int kb = (bb / (N / 32)) * 32;
    const int tx = tid & 31, ty = tid >> 5;
#pragma unroll
    for (int i2 = 0; i2 < 32; i2 += 8)
        tile[ty + i2][tx] = w[(size_t)(kb + ty + i2) * N + nb + tx];
    __syncthreads();
#pragma unroll
    for (int i2 = 0; i2 < 32; i2 += 8)
        oh[(size_t)(nb + ty + i2) * GEMM_K + kb + tx] =
            __float2half_rn(tile[tx][ty + i2]);
}

// ---------------------------------------------------------------------------
// HMMA 1-pass fp16 GEMM (round-16 config, plateau accepted): 128x128 tile,
// BK=64, 3-stage cp.async, 256 threads (8 warps 4x2, warp 32x64), 2 CTAs/SM,
// 2-deep register fragment pipeline.
// mode 0: bias + fp16 scatter (k hi, q hi*QSCALE, v hi)
// mode 1: bias + fp32 store
// ---------------------------------------------------------------------------
#define G_ROWB   144                    // 128B data + 16B pad
#define G_TILE   (128 * G_ROWB)         // 18432
#define G_STAGE  (2 * G_TILE)           // 36864 (Ah, Bh)
#define GEMM_SMEM (3 * G_STAGE)         // 110592 -> 2 CTAs/SM

struct GFrag { uint32_t a[2][4]; uint32_t b[4][4]; };   // 24 regs

__device__ __forceinline__ void g_load(GFrag& F, uint32_t bufBase, int s,
                                       int wr, int wc, int lane) {
    const int akb = s * 32 + ((lane >> 4) & 1) * 16;
    const int arow = wr * 32 + (lane & 7) + ((lane >> 3) & 1) * 8;
    ldm_x4(F.a[0], bufBase + (uint32_t)(arow * G_ROWB + akb));
    ldm_x4(F.a[1], bufBase + (uint32_t)((arow + 16) * G_ROWB + akb));
    const int bkb = s * 32 + ((lane >> 3) & 1) * 16;
    const int brow = wc * 64 + ((lane >> 4) & 1) * 8 + (lane & 7);
#pragma unroll
    for (int p2 = 0; p2 < 4; p2++)
        ldm_x4(F.b[p2], bufBase + (uint32_t)(G_TILE + (brow + p2 * 16) * G_ROWB + bkb));
}

__device__ __forceinline__ void g_mma(float acc[2][8][4], const GFrag& F) {
#pragma unroll
    for (int mt = 0; mt < 2; mt++)
#pragma unroll
        for (int nt = 0; nt < 8; nt++)
            mma_f16(acc[mt][nt], F.a[mt], &F.b[nt >> 1][(nt & 1) * 2]);
}

__global__ __launch_bounds__(256, 2)
void gemm_hmma(const float* __restrict__ bias, float* __restrict__ out,
               int mode) {
    extern __shared__ char smem[];
    const uint32_t sbase = (uint32_t)__cvta_generic_to_shared(smem);
    const int tid = threadIdx.x;
    const int lane = tid & 31, warp = tid >> 5;
    const int wr = warp & 3, wc = warp >> 2;      // 4x2 warp grid, warp 32x64
    const int rowBase = blockIdx.y * 128;
    const int colBase = blockIdx.x * 128;

    const __half *aSrc, *bSrc;
    if (mode == 0) { aSrc = g_x_hi;  bSrc = g_wq_hi; }
    else           { aSrc = g_ao_hi; bSrc = g_wp_hi; }

    float acc[2][8][4];
#pragma unroll
    for (int mt = 0; mt < 2; mt++)
#pragma unroll
        for (int nt = 0; nt < 8; nt++)
#pragma unroll
            for (int q = 0; q < 4; q++) acc[mt][nt][q] = 0.f;

    auto prefetch = [&](int chunk) {
        const int st = chunk % 3;
        const int k0 = chunk * 64;
        const int rb[2] = {rowBase, colBase};
        const __half* sv[2] = {aSrc, bSrc};
#pragma unroll
        for (int v = 0; v < 2; v++) {
#pragma unroll
            for (int it = 0; it < 4; it++) {
                int p = tid + it * 256;            // 0..1023
                int r = p >> 3, cp = p & 7;
                const __half* g =
                    sv[v] + (size_t)(rb[v] + r) * GEMM_K + k0 + cp * 8;
                uint32_t d = sbase + (uint32_t)(st * G_STAGE + v * G_TILE
                                                + r * G_ROWB + cp * 16);
                CP_ASYNC16(d, g);
            }
        }
        CP_COMMIT();
    };

    prefetch(0);
    prefetch(1);

    GFrag F0, F1;
    const int NC = GEMM_K / 64;          // 16
    for (int c = 0; c < NC; c++) {
        if (c + 1 < NC) { CP_WAIT1(); } else { CP_WAIT0(); }
        __syncthreads();
        if (c + 2 < NC) prefetch(c + 2);  // writes stage (c+2)%3 = (c-1)%3: safe

        const uint32_t bufBase = sbase + (uint32_t)((c % 3) * G_STAGE);
        g_load(F0, bufBase, 0, wr, wc, lane);
        g_load(F1, bufBase, 1, wr, wc, lane);  // in flight during s=0 MMAs
        g_mma(acc, F0);
        g_load(F0, bufBase, 2, wr, wc, lane);
        g_mma(acc, F1);
        g_load(F1, bufBase, 3, wr, wc, lane);
        g_mma(acc, F0);
        g_mma(acc, F1);
    }

    const int r0 = lane >> 2;
    const int c0 = (lane & 3) * 2;
#pragma unroll
    for (int mt = 0; mt < 2; mt++) {
#pragma unroll
        for (int nt = 0; nt < 8; nt++) {
            const int n0 = colBase + wc * 64 + nt * 8 + c0;
            const float b0 = bias[n0], b1 = bias[n0 + 1];
#pragma unroll
            for (int half = 0; half < 2; half++) {
                const int m = rowBase + wr * 32 + mt * 16 + r0 + half * 8;
                float f0 = acc[mt][nt][half * 2 + 0] + b0;
                float f1 = acc[mt][nt][half * 2 + 1] + b1;
                if (mode == 0) {
                    const int bb = m >> 11, t = m & 2047;
                    const int sec = n0 >> 10, cc = n0 & 1023;
                    const int h = cc >> 6, d0 = cc & 63;
                    size_t off = (((size_t)(bb * 16 + h)) * T_SZ + t) * 64 + d0;
                    if (sec == 1) {
                        *(uint32_t*)(g_q16h + off) = packh(f0 * QSCALE, f1 * QSCALE);
                    } else {
                        __half* dh = (sec == 0) ? g_k16h : g_v16h;
                        *(uint32_t*)(dh + off) = packh(f0, f1);
                    }
                } else {
                    float2 v; v.x = f0; v.y = f1;
                    *(float2*)(out + (size_t)m * C_SZ + n0) = v;
                }
            }
        }
    }
}

// ---------------------------------------------------------------------------
// Flash attention: 1-pass fp16, hoisted K fragments, exp2-domain softmax
// (scores arrive pre-multiplied by log2e via QSCALE -> bare exp2f).
// 256-row i-tiles, 8 warps x 32 rows. wei = K@Q^T: query-role = k (resident),
// key-role = q. S = Kh·Qh;  O = Ph·Vh.
// ---------------------------------------------------------------------------
#define AST   144
#define SQH_O 0
#define SKV_O (256 * AST)              // 36864
#define KVVAR (64 * AST)               // 9216
#define KVBUF (2 * KVVAR)              // 18432 (qh, vh)
#define ATT_SMEM (SKV_O + 2 * KVBUF)   // 73728

__global__ __launch_bounds__(256, 1)
void attn_hmma() {
    extern __shared__ char smem[];
    const uint32_t sbase = (uint32_t)__cvta_generic_to_shared(smem);
    const int tid = threadIdx.x;
    const int lane = tid & 31, w = tid >> 5;
    const int bh = blockIdx.x;
    const int it = (int)(gridDim.y - 1 - blockIdx.y);   // heavy blocks first

    const size_t hbo = (size_t)bh * T_SZ * 64;
    const __half* kvsrc[2] = {g_q16h + hbo, g_v16h + hbo};

    auto prefetchKV = [&](int jt) {
        const int buf = jt & 1;
#pragma unroll
        for (int i = 0; i < 4; i++) {
            int p = tid + i * 256;               // 0..1023
            int v = p >> 9, rem = p & 511;
            int r = rem >> 3, cp = rem & 7;
            const __half* src = kvsrc[v] + (size_t)(jt * 64 + r) * 64 + cp * 8;
            uint32_t dst = sbase + (uint32_t)(SKV_O + buf * KVBUF + v * KVVAR
                                              + r * AST + cp * 16);
            CP_ASYNC16(dst, src);
        }
        CP_COMMIT();
    };

    prefetchKV(0);

    // resident query-role tile (k hi), vectorized 16B staging
    {
        const __half* kh = g_k16h + hbo;
#pragma unroll
        for (int i = 0; i < 8; i++) {
            int p = tid + i * 256;               // 0..2047
            int r = p >> 3, c8 = p & 7;
            size_t go = (size_t)(it * 256 + r) * 64 + c8 * 8;
            uint4 v = *(const uint4*)(kh + go);
            *(uint4*)(smem + SQH_O + r * AST + c8 * 16) = v;
        }
    }
    __syncthreads();

    // Hoisted K fragments (jt-invariant)
    uint32_t kf[4][2][4];
    {
        const int arow = w * 32 + (lane & 7) + ((lane >> 3) & 1) * 8;
#pragma unroll
        for (int kk = 0; kk < 4; kk++) {
            const int ab = kk * 32 + ((lane >> 4) & 1) * 16;
            ldm_x4(kf[kk][0], sbase + (uint32_t)(SQH_O + arow * AST + ab));
            ldm_x4(kf[kk][1], sbase + (uint32_t)(SQH_O + (arow + 16) * AST + ab));
        }
    }

    float m[2][2], l[2][2];
#pragma unroll
    for (int mt = 0; mt < 2; mt++) { m[mt][0] = m[mt][1] = -1e30f; l[mt][0] = l[mt][1] = 0.f; }
    float O[2][8][4];
#pragma unroll
    for (int mt = 0; mt < 2; mt++)
#pragma unroll
        for (int dt = 0; dt < 8; dt++)
#pragma unroll
            for (int q = 0; q < 4; q++) O[mt][dt][q] = 0.f;

    const int iw = it * 256 + w * 32;
    const int jlast = 4 * it + 3;

    for (int jt = 0; jt <= jlast; jt++) {
        CP_WAIT0();
        __syncthreads();
        if (jt < jlast) prefetchKV(jt + 1);

        if (jt * 64 <= iw + 31) {
            const uint32_t kb = sbase + (uint32_t)(SKV_O + (jt & 1) * KVBUF);
            float s[2][8][4];
#pragma unroll
            for (int mt = 0; mt < 2; mt++)
#pragma unroll
                for (int nt = 0; nt < 8; nt++)
#pragma unroll
                    for (int q = 0; q < 4; q++) s[mt][nt][q] = 0.f;

            // ---- scores: S = Kh @ Qh^T (log2 domain) ----
#pragma unroll
            for (int kk = 0; kk < 4; kk++) {
                const int bb = kk * 32 + ((lane >> 3) & 1) * 16;
                const int br = ((lane >> 4) & 1) * 8 + (lane & 7);
#pragma unroll
                for (int np = 0; np < 4; np++) {
                    uint32_t qf[4];
                    ldm_x4(qf, kb + (uint32_t)((np * 16 + br) * AST + bb));
#pragma unroll
                    for (int mt = 0; mt < 2; mt++) {
                        mma_f16(s[mt][2 * np],     kf[kk][mt], qf + 0);
                        mma_f16(s[mt][2 * np + 1], kf[kk][mt], qf + 2);
                    }
                }
            }

            // ---- causal mask ----
            const int i0 = iw + (lane >> 2);
            if (jt * 64 + 63 > iw) {
#pragma unroll
                for (int mt = 0; mt < 2; mt++)
#pragma unroll
                    for (int nt = 0; nt < 8; nt++)
#pragma unroll
                        for (int q = 0; q < 4; q++) {
                            int j = jt * 64 + nt * 8 + (lane & 3) * 2 + (q & 1);
                            int i = i0 + mt * 16 + ((q >> 1) ? 8 : 0);
                            if (j > i) s[mt][nt][q] = -1e30f;
                        }
            }

            // ---- online softmax (exp2 domain) ----
#pragma unroll
            for (int mt = 0; mt < 2; mt++) {
                float mx0 = -1e30f, mx1 = -1e30f;
#pragma unroll
                for (int nt = 0; nt < 8; nt++) {
                    mx0 = fmaxf(mx0, fmaxf(s[mt][nt][0], s[mt][nt][1]));
                    mx1 = fmaxf(mx1, fmaxf(s[mt][nt][2], s[mt][nt][3]));
                }
                mx0 = fmaxf(mx0, __shfl_xor_sync(0xffffffffu, mx0, 1));
                mx0 = fmaxf(mx0, __shfl_xor_sync(0xffffffffu, mx0, 2));
                mx1 = fmaxf(mx1, __shfl_xor_sync(0xffffffffu, mx1, 1));
                mx1 = fmaxf(mx1, __shfl_xor_sync(0xffffffffu, mx1, 2));
                float mn0 = fmaxf(m[mt][0], mx0), mn1 = fmaxf(m[mt][1], mx1);
                float a0 = exp2f(m[mt][0] - mn0), a1 = exp2f(m[mt][1] - mn1);
                float sum0 = 0.f, sum1 = 0.f;
#pragma unroll
                for (int nt = 0; nt < 8; nt++) {
                    s[mt][nt][0] = exp2f(s[mt][nt][0] - mn0);
                    s[mt][nt][1] = exp2f(s[mt][nt][1] - mn0);
                    s[mt][nt][2] = exp2f(s[mt][nt][2] - mn1);
                    s[mt][nt][3] = exp2f(s[mt][nt][3] - mn1);
                    sum0 += s[mt][nt][0] + s[mt][nt][1];
                    sum1 += s[mt][nt][2] + s[mt][nt][3];
                }
                sum0 += __shfl_xor_sync(0xffffffffu, sum0, 1);
                sum0 += __shfl_xor_sync(0xffffffffu, sum0, 2);
                sum1 += __shfl_xor_sync(0xffffffffu, sum1, 1);
                sum1 += __shfl_xor_sync(0xffffffffu, sum1, 2);
                l[mt][0] = l[mt][0] * a0 + sum0;
                l[mt][1] = l[mt][1] * a1 + sum1;
                m[mt][0] = mn0;  m[mt][1] = mn1;
#pragma unroll
                for (int dt = 0; dt < 8; dt++) {
                    O[mt][dt][0] *= a0; O[mt][dt][1] *= a0;
                    O[mt][dt][2] *= a1; O[mt][dt][3] *= a1;
                }
            }

            // ---- PV: O += Ph @ Vh ----
#pragma unroll
            for (int kk = 0; kk < 4; kk++) {
                uint32_t pah[2][4];
#pragma unroll
                for (int mt = 0; mt < 2; mt++)
#pragma unroll
                    for (int t = 0; t < 4; t++) {
                        float f0 = s[mt][2 * kk + (t >> 1)][(t & 1) * 2 + 0];
                        float f1 = s[mt][2 * kk + (t >> 1)][(t & 1) * 2 + 1];
                        pah[mt][t] = packh(f0, f1);
                    }
                const int vrow = kk * 16 + (lane & 7) + ((lane >> 3) & 1) * 8;
                const int voff = ((lane >> 4) & 1) * 16;
#pragma unroll
                for (int dp = 0; dp < 4; dp++) {
                    uint32_t vh4[4];
                    ldm_x4t(vh4, kb + (uint32_t)(KVVAR + vrow * AST + dp * 32 + voff));
#pragma unroll
                    for (int mt = 0; mt < 2; mt++) {
                        mma_f16(O[mt][2 * dp],     pah[mt], vh4 + 0);
                        mma_f16(O[mt][2 * dp + 1], pah[mt], vh4 + 2);
                    }
                }
            }
        }
    }

    // epilogue: normalize, fp16 write [b][t][C]
    const int b = bh >> 4, h = bh & 15;
#pragma unroll
    for (int mt = 0; mt < 2; mt++) {
        const float inv0 = 1.f / l[mt][0], inv1 = 1.f / l[mt][1];
        const int i0 = iw + mt * 16 + (lane >> 2);
#pragma unroll
        for (int dt = 0; dt < 8; dt++) {
            const int col = h * 64 + dt * 8 + (lane & 3) * 2;
            {
                float f0 = O[mt][dt][0] * inv0, f1 = O[mt][dt][1] * inv0;
                size_t off = ((size_t)(b * T_SZ + i0)) * C_SZ + col;
                *(uint32_t*)(g_ao_hi + off) = packh(f0, f1);
            }
            {
                float f0 = O[mt][dt][2] * inv1, f1 = O[mt][dt][3] * inv1;
                size_t off = ((size_t)(b * T_SZ + i0 + 8)) * C_SZ + col;
                *(uint32_t*)(g_ao_hi + off) = packh(f0, f1);
            }
        }
    }
}

// ---------------------------------------------------------------------------
extern "C" void kernel_launch(void* const* d_in, const int* in_sizes, int n_in,
                              void* d_out, int out_size) {
    const float* x        = (const float*)d_in[0];
    const float* c_attn_w = (const float*)d_in[1];
    const float* c_attn_b = (const float*)d_in[2];
    const float* c_proj_w = (const float*)d_in[3];
    const float* c_proj_b = (const float*)d_in[4];
    float* out = (float*)d_out;

    prep_kernel<<<4096 + 3072 + 1024, 256>>>(x, c_attn_w, c_proj_w);

    cudaFuncSetAttribute(gemm_hmma,
                         cudaFuncAttributeMaxDynamicSharedMemorySize, GEMM_SMEM);
    cudaFuncSetAttribute(attn_hmma,
                         cudaFuncAttributeMaxDynamicSharedMemorySize, ATT_SMEM);

    // QKV: grid (24, 32)
    gemm_hmma<<<dim3(N_QKV / 128, M_ROWS / 128), 256, GEMM_SMEM>>>(
        c_attn_b, nullptr, 0);

    attn_hmma<<<dim3(32, T_SZ / 256), 256, ATT_SMEM>>>();

    // Proj: grid (8, 32)
    gemm_hmma<<<dim3(C_SZ / 128, M_ROWS / 128), 256, GEMM_SMEM>>>(
        c_proj_b, out, 1);
}